// round 6
// baseline (speedup 1.0000x reference)
#include <cuda_runtime.h>
#include <cstdint>

// FirstDeriv: per-node weighted least-squares gradient.
//   dv_k = c[nbr_k] - c[i], du_k = y[nbr_k] - y[i]   (masked if nbr == -1)
//   w_k  = 1 / (|dv_k|^2 + 1e-8)
//   A    = sum_k w_k dv_k dv_k^T   (3x3 sym),  B = sum_k w_k dv_k du_k
//   out[i] = solve(A + 1e-6 I, B)
//
// Structure:
//   detect_kernel:  runtime dtype detection for neighbor indices (JAX silently
//                   downgrades int64->int32 without x64 mode; reading int32 as
//                   int64 overruns the buffer -> round-2 crash).
//   pack_kernel:    (x,y,z,u) -> aligned float4 so each gather = 1 L2 sector.
//   firstderiv:     one warp per node; lane l handles neighbors 2l, 2l+1 via
//                   one vectorized index load (int2 / longlong2, both provably
//                   aligned); butterfly-reduce 9 sums; lane 0 solves the 3x3
//                   system in fp64 (Cramer) and writes.

#define EPS_W 1e-8f
#define LAM   1e-6

static __device__ float4 g_pack[262144];   // 4 MB static scratch (N = 200000)
static __device__ int    g_idx_is64;

__global__ void pack_kernel(const float* __restrict__ coords,
                            const float* __restrict__ y,
                            int n)
{
    int i = blockIdx.x * blockDim.x + threadIdx.x;
    if (i < n) {
        g_pack[i] = make_float4(coords[3 * i + 0],
                                coords[3 * i + 1],
                                coords[3 * i + 2],
                                y[i]);
    }
}

// Decide whether the neighbor buffer holds int64 or int32 indices.
// int32 data reinterpreted as int64 yields values outside [-1, n) with
// overwhelming probability over 2048 samples; genuine int64 indices never do.
__global__ void detect_kernel(const long long* __restrict__ nbr, int n,
                              int nsamp)
{
    __shared__ int bad;
    if (threadIdx.x == 0) bad = 0;
    __syncthreads();
    for (int i = threadIdx.x; i < nsamp; i += blockDim.x) {
        long long v = nbr[i];
        if (v < -1 || v >= (long long)n) bad = 1;
    }
    __syncthreads();
    if (threadIdx.x == 0) g_idx_is64 = bad ? 0 : 1;
}

__device__ __forceinline__ float warp_sum(float v)
{
#pragma unroll
    for (int o = 16; o > 0; o >>= 1)
        v += __shfl_xor_sync(0xffffffffu, v, o);
    return v;
}

__global__ void __launch_bounds__(256, 8)
firstderiv_kernel(const void* __restrict__ nbr_raw,
                  float* __restrict__ out,
                  int n, int K)
{
    const int warp_id = (blockIdx.x * blockDim.x + threadIdx.x) >> 5;
    const int lane    = threadIdx.x & 31;
    if (warp_id >= n) return;

    const int node = warp_id;
    const float4 ci = g_pack[node];

    const int is64 = g_idx_is64;   // uniform

    float a00 = 0.f, a01 = 0.f, a02 = 0.f, a11 = 0.f, a12 = 0.f, a22 = 0.f;
    float b0 = 0.f, b1 = 0.f, b2 = 0.f;

    // Lane l handles neighbors 2l and 2l+1 (one vectorized index load).
    // Outer loop generalizes to any even K (K = 64 -> single iteration).
    for (int base = 0; base < K; base += 64) {
        const int k = base + 2 * lane;
        long long i0 = -1, i1 = -1;
        if (k < K) {
            if (is64) {
                const longlong2* row2 =
                    (const longlong2*)((const long long*)nbr_raw + (size_t)node * K + k);
                longlong2 p = __ldg(row2);   // 16B-aligned: index is even
                i0 = p.x; i1 = p.y;
            } else {
                const int2* row2 =
                    (const int2*)((const int*)nbr_raw + (size_t)node * K + k);
                int2 p = __ldg(row2);        // 8B-aligned: index is even
                i0 = p.x; i1 = p.y;
            }
        }

        // Branchless clamp: invalid neighbors gather node 0 but get w = 0.
        const bool v0 = (i0 >= 0) && (i0 < n);
        const bool v1 = (i1 >= 0) && (i1 < n);
        const int  j0 = v0 ? (int)i0 : 0;
        const int  j1 = v1 ? (int)i1 : 0;

        // Front-batch both gathers (one 32B sector each, L2-resident).
        const float4 c0 = __ldg(&g_pack[j0]);
        const float4 c1 = __ldg(&g_pack[j1]);

#pragma unroll
        for (int h = 0; h < 2; ++h) {
            const float4 cn = (h == 0) ? c0 : c1;
            const float  vm = ((h == 0) ? v0 : v1) ? 1.f : 0.f;
            float dx = cn.x - ci.x;
            float dy = cn.y - ci.y;
            float dz = cn.z - ci.z;
            float du = cn.w - ci.w;
            float d2 = fmaf(dx, dx, fmaf(dy, dy, dz * dz));
            float w  = vm / (d2 + EPS_W);
            a00 = fmaf(w * dx, dx, a00);
            a01 = fmaf(w * dx, dy, a01);
            a02 = fmaf(w * dx, dz, a02);
            a11 = fmaf(w * dy, dy, a11);
            a12 = fmaf(w * dy, dz, a12);
            a22 = fmaf(w * dz, dz, a22);
            b0  = fmaf(w * dx, du, b0);
            b1  = fmaf(w * dy, du, b1);
            b2  = fmaf(w * dz, du, b2);
        }
    }

    a00 = warp_sum(a00); a01 = warp_sum(a01); a02 = warp_sum(a02);
    a11 = warp_sum(a11); a12 = warp_sum(a12); a22 = warp_sum(a22);
    b0  = warp_sum(b0);  b1  = warp_sum(b1);  b2  = warp_sum(b2);

    if (lane == 0) {
        // 3x3 symmetric solve (A + LAM*I) x = B via Cramer, in fp64.
        double A00 = (double)a00 + LAM;
        double A11 = (double)a11 + LAM;
        double A22 = (double)a22 + LAM;
        double A01 = a01, A02 = a02, A12 = a12;
        double B0 = b0, B1 = b1, B2 = b2;

        double c00 = A11 * A22 - A12 * A12;
        double c01 = A02 * A12 - A01 * A22;
        double c02 = A01 * A12 - A02 * A11;
        double det = A00 * c00 + A01 * c01 + A02 * c02;
        double inv = 1.0 / det;

        double c11 = A00 * A22 - A02 * A02;
        double c12 = A01 * A02 - A00 * A12;
        double c22 = A00 * A11 - A01 * A01;

        double x0 = (c00 * B0 + c01 * B1 + c02 * B2) * inv;
        double x1 = (c01 * B0 + c11 * B1 + c12 * B2) * inv;
        double x2 = (c02 * B0 + c12 * B1 + c22 * B2) * inv;

        out[3 * node + 0] = (float)x0;
        out[3 * node + 1] = (float)x1;
        out[3 * node + 2] = (float)x2;
    }
}

extern "C" void kernel_launch(void* const* d_in, const int* in_sizes, int n_in,
                              void* d_out, int out_size)
{
    // Identify inputs by element count, not position:
    //   coords: N*3 = 600000, neighbors: N*K = 12800000, y: N = 200000.
    int i_nbr = 0;
    for (int i = 1; i < n_in; ++i)
        if (in_sizes[i] > in_sizes[i_nbr]) i_nbr = i;
    int i_coords = -1, i_y = -1;
    for (int i = 0; i < n_in; ++i) {
        if (i == i_nbr) continue;
        if (i_coords < 0) i_coords = i;
        else if (in_sizes[i] > in_sizes[i_coords]) { i_y = i_coords; i_coords = i; }
        else i_y = i;
    }

    const float* coords = (const float*)d_in[i_coords];
    const void*  nbrs   = d_in[i_nbr];
    const float* y      = (const float*)d_in[i_y];
    float*       out    = (float*)d_out;

    const int n = in_sizes[i_coords] / 3;        // 200000
    const int K = in_sizes[i_nbr] / n;           // 64

    // Sample count for dtype detection. Reading nsamp int64 touches
    // 2*nsamp int32-slots; cap so it is in-bounds under EITHER dtype.
    int nsamp = in_sizes[i_nbr] / 2;
    if (nsamp > 2048) nsamp = 2048;
    if (nsamp < 1) nsamp = 1;
    detect_kernel<<<1, 256>>>((const long long*)nbrs, n, nsamp);

    pack_kernel<<<(n + 255) / 256, 256>>>(coords, y, n);

    // one warp per node, 8 warps per block
    int blocks = (n + 7) / 8;
    firstderiv_kernel<<<blocks, 256>>>(nbrs, out, n, K);
}

// round 8
// speedup vs baseline: 4.3521x; 4.3521x over previous
#include <cuda_runtime.h>
#include <cstdint>

// FirstDeriv: per-node weighted least-squares gradient.
//   dv_k = c[nbr_k] - c[i], du_k = y[nbr_k] - y[i]   (masked if nbr == -1)
//   w_k  = 1 / (|dv_k|^2 + 1e-8)
//   A    = sum_k w_k dv_k dv_k^T   (3x3 sym),  B = sum_k w_k dv_k du_k
//   out[i] = solve(A + 1e-6 I, B)
//
// R6 post-mortem: fp64 Cramer epilogue cost ~460us (sm_103a fp64 rt ~18.4
// cyc/SM). Solve is now fp32 (rel_err budget 1e-3, fp64 gave 3.4e-7 -> huge
// headroom). detect_kernel parallelized.

#define EPS_W 1e-8f
#define LAM   1e-6f

static __device__ float4 g_pack[262144];   // 4 MB static scratch (N = 200000)
static __device__ int    g_idx_is64;

__global__ void pack_kernel(const float* __restrict__ coords,
                            const float* __restrict__ y,
                            int n)
{
    int i = blockIdx.x * blockDim.x + threadIdx.x;
    if (i < n) {
        g_pack[i] = make_float4(coords[3 * i + 0],
                                coords[3 * i + 1],
                                coords[3 * i + 2],
                                y[i]);
    }
}

// Decide whether the neighbor buffer holds int64 or int32 indices.
// int32 data reinterpreted as int64 falls outside [-1, n) with overwhelming
// probability over 2048 samples; genuine int64 indices never do.
// g_idx_is64 is pre-set to 1; any out-of-range sample clears it (racy
// redundant stores of the same value — benign).
__global__ void init_flag_kernel() { g_idx_is64 = 1; }

__global__ void detect_kernel(const long long* __restrict__ nbr, int n,
                              int nsamp)
{
    int i = blockIdx.x * blockDim.x + threadIdx.x;
    if (i < nsamp) {
        long long v = nbr[i];
        if (v < -1 || v >= (long long)n) g_idx_is64 = 0;
    }
}

__device__ __forceinline__ float warp_sum(float v)
{
#pragma unroll
    for (int o = 16; o > 0; o >>= 1)
        v += __shfl_xor_sync(0xffffffffu, v, o);
    return v;
}

__global__ void __launch_bounds__(256, 8)
firstderiv_kernel(const void* __restrict__ nbr_raw,
                  float* __restrict__ out,
                  int n, int K)
{
    const int warp_id = (blockIdx.x * blockDim.x + threadIdx.x) >> 5;
    const int lane    = threadIdx.x & 31;
    if (warp_id >= n) return;

    const int node = warp_id;
    const float4 ci = g_pack[node];

    const int is64 = g_idx_is64;   // uniform

    float a00 = 0.f, a01 = 0.f, a02 = 0.f, a11 = 0.f, a12 = 0.f, a22 = 0.f;
    float b0 = 0.f, b1 = 0.f, b2 = 0.f;

    // Lane l handles neighbors 2l and 2l+1 (one vectorized index load).
    // Outer loop generalizes to any even K (K = 64 -> single iteration).
    for (int base = 0; base < K; base += 64) {
        const int k = base + 2 * lane;
        long long i0 = -1, i1 = -1;
        if (k < K) {
            if (is64) {
                const longlong2* row2 =
                    (const longlong2*)((const long long*)nbr_raw + (size_t)node * K + k);
                longlong2 p = __ldg(row2);   // 16B-aligned: index is even
                i0 = p.x; i1 = p.y;
            } else {
                const int2* row2 =
                    (const int2*)((const int*)nbr_raw + (size_t)node * K + k);
                int2 p = __ldg(row2);        // 8B-aligned: index is even
                i0 = p.x; i1 = p.y;
            }
        }

        // Branchless clamp: invalid neighbors gather node 0 but get w = 0.
        const bool v0 = (i0 >= 0) && (i0 < n);
        const bool v1 = (i1 >= 0) && (i1 < n);
        const int  j0 = v0 ? (int)i0 : 0;
        const int  j1 = v1 ? (int)i1 : 0;

        // Front-batch both gathers (one 32B sector each, L2-resident).
        const float4 c0 = __ldg(&g_pack[j0]);
        const float4 c1 = __ldg(&g_pack[j1]);

#pragma unroll
        for (int h = 0; h < 2; ++h) {
            const float4 cn = (h == 0) ? c0 : c1;
            const float  vm = ((h == 0) ? v0 : v1) ? 1.f : 0.f;
            float dx = cn.x - ci.x;
            float dy = cn.y - ci.y;
            float dz = cn.z - ci.z;
            float du = cn.w - ci.w;
            float d2 = fmaf(dx, dx, fmaf(dy, dy, dz * dz));
            float w  = vm / (d2 + EPS_W);
            a00 = fmaf(w * dx, dx, a00);
            a01 = fmaf(w * dx, dy, a01);
            a02 = fmaf(w * dx, dz, a02);
            a11 = fmaf(w * dy, dy, a11);
            a12 = fmaf(w * dy, dz, a12);
            a22 = fmaf(w * dz, dz, a22);
            b0  = fmaf(w * dx, du, b0);
            b1  = fmaf(w * dy, du, b1);
            b2  = fmaf(w * dz, du, b2);
        }
    }

    a00 = warp_sum(a00); a01 = warp_sum(a01); a02 = warp_sum(a02);
    a11 = warp_sum(a11); a12 = warp_sum(a12); a22 = warp_sum(a22);
    b0  = warp_sum(b0);  b1  = warp_sum(b1);  b2  = warp_sum(b2);

    if (lane == 0) {
        // 3x3 symmetric solve (A + LAM*I) x = B via Cramer, in fp32.
        // A is weighted SPD + Tikhonov => benign conditioning; fp64 measured
        // rel_err 3.4e-7 vs 1e-3 budget, fp32 has ample headroom.
        float A00 = a00 + LAM;
        float A11 = a11 + LAM;
        float A22 = a22 + LAM;
        float A01 = a01, A02 = a02, A12 = a12;

        float c00 = fmaf(A11, A22, -A12 * A12);
        float c01 = fmaf(A02, A12, -A01 * A22);
        float c02 = fmaf(A01, A12, -A02 * A11);
        float det = fmaf(A00, c00, fmaf(A01, c01, A02 * c02));
        float inv = 1.0f / det;

        float c11 = fmaf(A00, A22, -A02 * A02);
        float c12 = fmaf(A01, A02, -A00 * A12);
        float c22 = fmaf(A00, A11, -A01 * A01);

        float x0 = fmaf(c00, b0, fmaf(c01, b1, c02 * b2)) * inv;
        float x1 = fmaf(c01, b0, fmaf(c11, b1, c12 * b2)) * inv;
        float x2 = fmaf(c02, b0, fmaf(c12, b1, c22 * b2)) * inv;

        out[3 * node + 0] = x0;
        out[3 * node + 1] = x1;
        out[3 * node + 2] = x2;
    }
}

extern "C" void kernel_launch(void* const* d_in, const int* in_sizes, int n_in,
                              void* d_out, int out_size)
{
    // Identify inputs by element count, not position:
    //   coords: N*3 = 600000, neighbors: N*K = 12800000, y: N = 200000.
    int i_nbr = 0;
    for (int i = 1; i < n_in; ++i)
        if (in_sizes[i] > in_sizes[i_nbr]) i_nbr = i;
    int i_coords = -1, i_y = -1;
    for (int i = 0; i < n_in; ++i) {
        if (i == i_nbr) continue;
        if (i_coords < 0) i_coords = i;
        else if (in_sizes[i] > in_sizes[i_coords]) { i_y = i_coords; i_coords = i; }
        else i_y = i;
    }

    const float* coords = (const float*)d_in[i_coords];
    const void*  nbrs   = d_in[i_nbr];
    const float* y      = (const float*)d_in[i_y];
    float*       out    = (float*)d_out;

    const int n = in_sizes[i_coords] / 3;        // 200000
    const int K = in_sizes[i_nbr] / n;           // 64

    // Sample count for dtype detection. Reading nsamp int64 touches
    // 2*nsamp int32-slots; cap so it is in-bounds under EITHER dtype.
    int nsamp = in_sizes[i_nbr] / 2;
    if (nsamp > 2048) nsamp = 2048;
    if (nsamp < 1) nsamp = 1;
    init_flag_kernel<<<1, 1>>>();
    detect_kernel<<<(nsamp + 255) / 256, 256>>>((const long long*)nbrs, n, nsamp);

    pack_kernel<<<(n + 255) / 256, 256>>>(coords, y, n);

    // one warp per node, 8 warps per block
    int blocks = (n + 7) / 8;
    firstderiv_kernel<<<blocks, 256>>>(nbrs, out, n, K);
}

// round 10
// speedup vs baseline: 9.0976x; 2.0904x over previous
#include <cuda_runtime.h>
#include <cstdint>

// FirstDeriv: per-node weighted least-squares gradient.
//   dv_k = c[nbr_k] - c[i], du_k = y[nbr_k] - y[i]   (masked if nbr == -1)
//   w_k  = 1 / (|dv_k|^2 + 1e-8)
//   A    = sum_k w_k dv_k dv_k^T (3x3 sym),  B = sum_k w_k dv_k du_k
//   out[i] = solve(A + 1e-6 I, B)   [fp32 Cramer; rel_err 3.5e-7 measured]
//
// R8 ncu (129.5us): L1tex wavefront replay is the binder (L1=78.5%,
// L2=58.3%, DRAM=5.5%). 12.8M random float4 gathers -> ~12.8M wavefronts,
// ~94us floor at ~2.07 cyc/wf. Hypothesis under test: half-warp per node
// with 4 neighbors/lane (gather MLP 2->4) closes part of the 21.5% L1tex
// idle; predicted 102-115us.

#define EPS_W 1e-8f
#define LAM   1e-6f

static __device__ float4 g_pack[262144];   // 4 MB static scratch (N = 200000)
static __device__ int    g_idx_is64;

// pack_kernel also initializes the dtype flag (thread 0) so no separate
// init launch is needed; detect_kernel runs after it in stream order.
__global__ void pack_kernel(const float* __restrict__ coords,
                            const float* __restrict__ y,
                            int n)
{
    int i = blockIdx.x * blockDim.x + threadIdx.x;
    if (i == 0 && blockIdx.x == 0) g_idx_is64 = 1;
    if (i < n) {
        g_pack[i] = make_float4(coords[3 * i + 0],
                                coords[3 * i + 1],
                                coords[3 * i + 2],
                                y[i]);
    }
}

// int32 data reinterpreted as int64 falls outside [-1, n) with overwhelming
// probability over 2048 samples; genuine int64 indices never do. Racy
// redundant stores of the same value are benign.
__global__ void detect_kernel(const long long* __restrict__ nbr, int n,
                              int nsamp)
{
    int i = blockIdx.x * blockDim.x + threadIdx.x;
    if (i < nsamp) {
        long long v = nbr[i];
        if (v < -1 || v >= (long long)n) g_idx_is64 = 0;
    }
}

// Butterfly reduce over 16-lane half-warps (offsets <= 8 stay in the half).
__device__ __forceinline__ float half_sum(float v)
{
#pragma unroll
    for (int o = 8; o > 0; o >>= 1)
        v += __shfl_xor_sync(0xffffffffu, v, o);
    return v;
}

__global__ void __launch_bounds__(256)
firstderiv_kernel(const void* __restrict__ nbr_raw,
                  float* __restrict__ out,
                  int n, int K)
{
    const int warp_id = (blockIdx.x * blockDim.x + threadIdx.x) >> 5;
    const int lane    = threadIdx.x & 31;
    const int half    = lane >> 4;        // 0 or 1: which node in this warp
    const int hl      = lane & 15;        // lane within the half

    const int node_raw = warp_id * 2 + half;
    if (warp_id * 2 >= n) return;         // whole warp out of range
    const int node = (node_raw < n) ? node_raw : (n - 1);  // clamp for loads
    const bool live = (node_raw < n);

    const float4 ci = g_pack[node];
    const int is64 = g_idx_is64;          // uniform

    float a00 = 0.f, a01 = 0.f, a02 = 0.f, a11 = 0.f, a12 = 0.f, a22 = 0.f;
    float b0 = 0.f, b1 = 0.f, b2 = 0.f;

    // hl handles neighbors 4*hl .. 4*hl+3 (16 lanes x 4 = 64 per K-chunk).
    for (int base = 0; base < K; base += 64) {
        const int k = base + 4 * hl;
        long long i0 = -1, i1 = -1, i2 = -1, i3 = -1;
        if (k < K) {
            if (is64) {
                const long long* row = (const long long*)nbr_raw + (size_t)node * K + k;
                longlong2 p0 = __ldg((const longlong2*)row);       // 16B aligned (k%4==0)
                longlong2 p1 = __ldg((const longlong2*)(row + 2));
                i0 = p0.x; i1 = p0.y; i2 = p1.x; i3 = p1.y;
            } else {
                const int* row = (const int*)nbr_raw + (size_t)node * K + k;
                int4 p = __ldg((const int4*)row);                  // 16B aligned (k%4==0)
                i0 = p.x; i1 = p.y; i2 = p.z; i3 = p.w;
            }
        }

        // Branchless clamp: invalid neighbors gather node 0 but get w = 0.
        const bool v0 = (i0 >= 0) && (i0 < n);
        const bool v1 = (i1 >= 0) && (i1 < n);
        const bool v2 = (i2 >= 0) && (i2 < n);
        const bool v3 = (i3 >= 0) && (i3 < n);
        const int  j0 = v0 ? (int)i0 : 0;
        const int  j1 = v1 ? (int)i1 : 0;
        const int  j2 = v2 ? (int)i2 : 0;
        const int  j3 = v3 ? (int)i3 : 0;

        // Front-batch 4 independent gathers (MLP=4, one 32B sector each).
        const float4 c0 = __ldg(&g_pack[j0]);
        const float4 c1 = __ldg(&g_pack[j1]);
        const float4 c2 = __ldg(&g_pack[j2]);
        const float4 c3 = __ldg(&g_pack[j3]);

        const float4 cs[4] = {c0, c1, c2, c3};
        const bool   vs[4] = {v0, v1, v2, v3};
#pragma unroll
        for (int h = 0; h < 4; ++h) {
            const float4 cn = cs[h];
            const float  vm = vs[h] ? 1.f : 0.f;
            float dx = cn.x - ci.x;
            float dy = cn.y - ci.y;
            float dz = cn.z - ci.z;
            float du = cn.w - ci.w;
            float d2 = fmaf(dx, dx, fmaf(dy, dy, dz * dz));
            float w  = vm / (d2 + EPS_W);
            a00 = fmaf(w * dx, dx, a00);
            a01 = fmaf(w * dx, dy, a01);
            a02 = fmaf(w * dx, dz, a02);
            a11 = fmaf(w * dy, dy, a11);
            a12 = fmaf(w * dy, dz, a12);
            a22 = fmaf(w * dz, dz, a22);
            b0  = fmaf(w * dx, du, b0);
            b1  = fmaf(w * dy, du, b1);
            b2  = fmaf(w * dz, du, b2);
        }
    }

    a00 = half_sum(a00); a01 = half_sum(a01); a02 = half_sum(a02);
    a11 = half_sum(a11); a12 = half_sum(a12); a22 = half_sum(a22);
    b0  = half_sum(b0);  b1  = half_sum(b1);  b2  = half_sum(b2);

    if (hl == 0 && live) {
        // 3x3 symmetric solve (A + LAM*I) x = B via Cramer, fp32.
        float A00 = a00 + LAM;
        float A11 = a11 + LAM;
        float A22 = a22 + LAM;
        float A01 = a01, A02 = a02, A12 = a12;

        float c00 = fmaf(A11, A22, -A12 * A12);
        float c01 = fmaf(A02, A12, -A01 * A22);
        float c02 = fmaf(A01, A12, -A02 * A11);
        float det = fmaf(A00, c00, fmaf(A01, c01, A02 * c02));
        float inv = 1.0f / det;

        float c11 = fmaf(A00, A22, -A02 * A02);
        float c12 = fmaf(A01, A02, -A00 * A12);
        float c22 = fmaf(A00, A11, -A01 * A01);

        float x0 = fmaf(c00, b0, fmaf(c01, b1, c02 * b2)) * inv;
        float x1 = fmaf(c01, b0, fmaf(c11, b1, c12 * b2)) * inv;
        float x2 = fmaf(c02, b0, fmaf(c12, b1, c22 * b2)) * inv;

        out[3 * node_raw + 0] = x0;
        out[3 * node_raw + 1] = x1;
        out[3 * node_raw + 2] = x2;
    }
}

extern "C" void kernel_launch(void* const* d_in, const int* in_sizes, int n_in,
                              void* d_out, int out_size)
{
    // Identify inputs by element count, not position:
    //   coords: N*3 = 600000, neighbors: N*K = 12800000, y: N = 200000.
    int i_nbr = 0;
    for (int i = 1; i < n_in; ++i)
        if (in_sizes[i] > in_sizes[i_nbr]) i_nbr = i;
    int i_coords = -1, i_y = -1;
    for (int i = 0; i < n_in; ++i) {
        if (i == i_nbr) continue;
        if (i_coords < 0) i_coords = i;
        else if (in_sizes[i] > in_sizes[i_coords]) { i_y = i_coords; i_coords = i; }
        else i_y = i;
    }

    const float* coords = (const float*)d_in[i_coords];
    const void*  nbrs   = d_in[i_nbr];
    const float* y      = (const float*)d_in[i_y];
    float*       out    = (float*)d_out;

    const int n = in_sizes[i_coords] / 3;        // 200000
    const int K = in_sizes[i_nbr] / n;           // 64

    pack_kernel<<<(n + 255) / 256, 256>>>(coords, y, n);

    // Reading nsamp int64 touches 2*nsamp int32-slots; in-bounds either way.
    int nsamp = in_sizes[i_nbr] / 2;
    if (nsamp > 2048) nsamp = 2048;
    if (nsamp < 1) nsamp = 1;
    detect_kernel<<<(nsamp + 255) / 256, 256>>>((const long long*)nbrs, n, nsamp);

    // one warp per 2 nodes (16 lanes each), 8 warps per block
    int nwarps = (n + 1) / 2;
    int blocks = (nwarps + 7) / 8;
    firstderiv_kernel<<<blocks, 256>>>(nbrs, out, n, K);
}

// round 15
// speedup vs baseline: 10.0992x; 1.1101x over previous
#include <cuda_runtime.h>
#include <cstdint>

// FirstDeriv: per-node weighted least-squares gradient.
//   dv_k = c[nbr_k] - c[i], du_k = y[nbr_k] - y[i]   (masked if nbr == -1)
//   w_k  = 1 / (|dv_k|^2 + 1e-8)
//   A    = sum_k w_k dv_k dv_k^T (3x3 sym),  B = sum_k w_k dv_k du_k
//   out[i] = solve(A + 1e-6 I, B)   [fp32 Cramer; rel_err 3.5e-7 measured]
//
// R10 (62.0us): MLP 2->4 gave 2.1x => R8 was issue-limited, not wavefront-
// saturated. Wavefront floor = 12.8M wf / 148 SM / ~1.95GHz ~= 44us; main
// kernel is ~54us (~80% of roofline). Under test: MLP 4->8 (8 lanes/node),
// detect folded into pack (one launch fewer), pack vectorized (4 nodes/thr).

#define EPS_W 1e-8f
#define LAM   1e-6f

static __device__ float4 g_pack[262144];   // 4 MB static scratch (N = 200000)
// Statically 1; only ever CLEARED by detection (deterministic across graph
// replays: int32 data re-clears every run, int64 data never writes).
static __device__ int g_idx_is64 = 1;

// Packs (x,y,z,u) into float4 AND samples the neighbor buffer for dtype
// detection (first nsamp threads). 4 nodes per thread, vectorized loads.
__global__ void pack_kernel(const float* __restrict__ coords,
                            const float* __restrict__ y,
                            const long long* __restrict__ nbr,
                            int n, int nsamp)
{
    const int t = blockIdx.x * blockDim.x + threadIdx.x;

    // dtype detection: int32 data reinterpreted as int64 falls outside
    // [-1, n) with overwhelming probability over 2048 samples.
    if (t < nsamp) {
        long long v = __ldg(&nbr[t]);
        if (v < -1 || v >= (long long)n) g_idx_is64 = 0;
    }

    const int base = t * 4;
    if (base + 3 < n) {
        const float4* c4 = (const float4*)(coords) + 3 * t;  // 48B per thread
        float4 p0 = __ldg(&c4[0]);
        float4 p1 = __ldg(&c4[1]);
        float4 p2 = __ldg(&c4[2]);
        float4 yv = __ldg((const float4*)y + t);
        g_pack[base + 0] = make_float4(p0.x, p0.y, p0.z, yv.x);
        g_pack[base + 1] = make_float4(p0.w, p1.x, p1.y, yv.y);
        g_pack[base + 2] = make_float4(p1.z, p1.w, p2.x, yv.z);
        g_pack[base + 3] = make_float4(p2.y, p2.z, p2.w, yv.w);
    } else if (base < n) {
        for (int i = base; i < n; ++i)
            g_pack[i] = make_float4(coords[3 * i + 0], coords[3 * i + 1],
                                    coords[3 * i + 2], y[i]);
    }
}

// Butterfly reduce over 8-lane groups (xor offsets 4,2,1 stay in-group).
__device__ __forceinline__ float oct_sum(float v)
{
#pragma unroll
    for (int o = 4; o > 0; o >>= 1)
        v += __shfl_xor_sync(0xffffffffu, v, o);
    return v;
}

__global__ void __launch_bounds__(256)
firstderiv_kernel(const void* __restrict__ nbr_raw,
                  float* __restrict__ out,
                  int n, int K)
{
    const int warp_id = (blockIdx.x * blockDim.x + threadIdx.x) >> 5;
    const int lane    = threadIdx.x & 31;
    const int sub     = lane >> 3;        // 0..3: which node in this warp
    const int sl      = lane & 7;         // lane within the 8-lane group

    const int node_raw = warp_id * 4 + sub;
    if (warp_id * 4 >= n) return;         // whole warp out of range
    const int node = (node_raw < n) ? node_raw : (n - 1);  // clamp for loads
    const bool live = (node_raw < n);

    const float4 ci = g_pack[node];
    const int is64 = g_idx_is64;          // uniform

    float a00 = 0.f, a01 = 0.f, a02 = 0.f, a11 = 0.f, a12 = 0.f, a22 = 0.f;
    float b0 = 0.f, b1 = 0.f, b2 = 0.f;

    // sl handles neighbors 8*sl .. 8*sl+7 (8 lanes x 8 = 64 per K-chunk).
    for (int base = 0; base < K; base += 64) {
        const int k = base + 8 * sl;
        long long idx[8];
#pragma unroll
        for (int h = 0; h < 8; ++h) idx[h] = -1;
        if (k < K) {
            if (is64) {
                const long long* row = (const long long*)nbr_raw + (size_t)node * K + k;
#pragma unroll
                for (int h = 0; h < 4; ++h) {
                    longlong2 p = __ldg((const longlong2*)(row + 2 * h)); // 16B aligned
                    idx[2 * h] = p.x; idx[2 * h + 1] = p.y;
                }
            } else {
                const int* row = (const int*)nbr_raw + (size_t)node * K + k;
                int4 p0 = __ldg((const int4*)row);        // 16B aligned (k%8==0)
                int4 p1 = __ldg((const int4*)(row + 4));
                idx[0] = p0.x; idx[1] = p0.y; idx[2] = p0.z; idx[3] = p0.w;
                idx[4] = p1.x; idx[5] = p1.y; idx[6] = p1.z; idx[7] = p1.w;
            }
        }

        bool vs[8];
        int  js[8];
#pragma unroll
        for (int h = 0; h < 8; ++h) {
            vs[h] = (idx[h] >= 0) && (idx[h] < n);
            js[h] = vs[h] ? (int)idx[h] : 0;
        }

        // Front-batch 8 independent gathers (MLP=8, one 32B sector each).
        float4 cs[8];
#pragma unroll
        for (int h = 0; h < 8; ++h) cs[h] = __ldg(&g_pack[js[h]]);

#pragma unroll
        for (int h = 0; h < 8; ++h) {
            const float4 cn = cs[h];
            const float  vm = vs[h] ? 1.f : 0.f;
            float dx = cn.x - ci.x;
            float dy = cn.y - ci.y;
            float dz = cn.z - ci.z;
            float du = cn.w - ci.w;
            float d2 = fmaf(dx, dx, fmaf(dy, dy, dz * dz));
            float w  = vm / (d2 + EPS_W);
            a00 = fmaf(w * dx, dx, a00);
            a01 = fmaf(w * dx, dy, a01);
            a02 = fmaf(w * dx, dz, a02);
            a11 = fmaf(w * dy, dy, a11);
            a12 = fmaf(w * dy, dz, a12);
            a22 = fmaf(w * dz, dz, a22);
            b0  = fmaf(w * dx, du, b0);
            b1  = fmaf(w * dy, du, b1);
            b2  = fmaf(w * dz, du, b2);
        }
    }

    a00 = oct_sum(a00); a01 = oct_sum(a01); a02 = oct_sum(a02);
    a11 = oct_sum(a11); a12 = oct_sum(a12); a22 = oct_sum(a22);
    b0  = oct_sum(b0);  b1  = oct_sum(b1);  b2  = oct_sum(b2);

    if (sl == 0 && live) {
        // 3x3 symmetric solve (A + LAM*I) x = B via Cramer, fp32.
        float A00 = a00 + LAM;
        float A11 = a11 + LAM;
        float A22 = a22 + LAM;
        float A01 = a01, A02 = a02, A12 = a12;

        float c00 = fmaf(A11, A22, -A12 * A12);
        float c01 = fmaf(A02, A12, -A01 * A22);
        float c02 = fmaf(A01, A12, -A02 * A11);
        float det = fmaf(A00, c00, fmaf(A01, c01, A02 * c02));
        float inv = 1.0f / det;

        float c11 = fmaf(A00, A22, -A02 * A02);
        float c12 = fmaf(A01, A02, -A00 * A12);
        float c22 = fmaf(A00, A11, -A01 * A01);

        float x0 = fmaf(c00, b0, fmaf(c01, b1, c02 * b2)) * inv;
        float x1 = fmaf(c01, b0, fmaf(c11, b1, c12 * b2)) * inv;
        float x2 = fmaf(c02, b0, fmaf(c12, b1, c22 * b2)) * inv;

        out[3 * node_raw + 0] = x0;
        out[3 * node_raw + 1] = x1;
        out[3 * node_raw + 2] = x2;
    }
}

extern "C" void kernel_launch(void* const* d_in, const int* in_sizes, int n_in,
                              void* d_out, int out_size)
{
    // Identify inputs by element count, not position:
    //   coords: N*3 = 600000, neighbors: N*K = 12800000, y: N = 200000.
    int i_nbr = 0;
    for (int i = 1; i < n_in; ++i)
        if (in_sizes[i] > in_sizes[i_nbr]) i_nbr = i;
    int i_coords = -1, i_y = -1;
    for (int i = 0; i < n_in; ++i) {
        if (i == i_nbr) continue;
        if (i_coords < 0) i_coords = i;
        else if (in_sizes[i] > in_sizes[i_coords]) { i_y = i_coords; i_coords = i; }
        else i_y = i;
    }

    const float* coords = (const float*)d_in[i_coords];
    const void*  nbrs   = d_in[i_nbr];
    const float* y      = (const float*)d_in[i_y];
    float*       out    = (float*)d_out;

    const int n = in_sizes[i_coords] / 3;        // 200000
    const int K = in_sizes[i_nbr] / n;           // 64

    // Reading nsamp int64 touches 2*nsamp int32-slots; in-bounds either way.
    int nsamp = in_sizes[i_nbr] / 2;
    if (nsamp > 2048) nsamp = 2048;
    if (nsamp < 1) nsamp = 1;

    // pack + detect fused: one prologue launch.
    int pack_threads = (n + 3) / 4;
    pack_kernel<<<(pack_threads + 255) / 256, 256>>>(
        coords, y, (const long long*)nbrs, n, nsamp);

    // one warp per 4 nodes (8 lanes each), 8 warps per block
    int nwarps = (n + 3) / 4;
    int blocks = (nwarps + 7) / 8;
    firstderiv_kernel<<<blocks, 256>>>(nbrs, out, n, K);
}